// round 6
// baseline (speedup 1.0000x reference)
#include <cuda_runtime.h>
#include <cstdint>

#define NN 100000
#define NE 1600000
#define FDIM 64
#define NB_SCAN 98   // ceil(NN/1024)

// ---------------- scratch (no allocation allowed) ----------------
__device__ float g_B1[NN * FDIM];
__device__ float g_B2[NN * FDIM];
__device__ float g_B3[NN * FDIM];
__device__ float g_H [NN * FDIM];
__device__ int   g_srcA[NE];         // CSR (by dst): src indices
__device__ float g_wA[NE];           // CSR (by dst): edge weights
__device__ int   g_degS[NN];
__device__ int   g_cntD[NN];
__device__ int   g_rowStart[NN + 1];
__device__ int   g_cursor[NN];
__device__ int   g_blockSums[128];
__device__ int   g_blockOffs[128];
__device__ float g_dinv[NN];

__device__ __forceinline__ const float* pick(int s, const float* x) {
    switch (s) {
        case 1: return g_B1;
        case 2: return g_B2;
        case 3: return g_B3;
        case 4: return g_H;
        default: return x;
    }
}
__device__ __forceinline__ float* pickw(int s, float* o) {
    switch (s) {
        case 1: return g_B1;
        case 2: return g_B2;
        case 3: return g_B3;
        case 4: return g_H;
        default: return o;
    }
}

// ---------------- CSR build ----------------
__global__ void zero_kernel() {
    int i = blockIdx.x * blockDim.x + threadIdx.x;
    if (i < NN) { g_degS[i] = 0; g_cntD[i] = 0; }
}

__global__ void hist_kernel(const int* __restrict__ src, const int* __restrict__ dst) {
    for (int i = blockIdx.x * blockDim.x + threadIdx.x; i < NE; i += gridDim.x * blockDim.x) {
        atomicAdd(&g_degS[src[i]], 1);
        atomicAdd(&g_cntD[dst[i]], 1);
    }
}

// scan of cntD + dinv computation (independent, fused to save a launch)
__global__ void scan1_kernel() {
    __shared__ int sb[1024];
    int i = blockIdx.x * 1024 + threadIdx.x;
    if (i < NN) {
        int d = g_degS[i];
        g_dinv[i] = (d > 0) ? rsqrtf((float)d) : 0.0f;
    }
    int v = (i < NN) ? g_cntD[i] : 0;
    sb[threadIdx.x] = v;
    __syncthreads();
    for (int off = 1; off < 1024; off <<= 1) {
        int t = (threadIdx.x >= off) ? sb[threadIdx.x - off] : 0;
        __syncthreads();
        sb[threadIdx.x] += t;
        __syncthreads();
    }
    if (i < NN) g_rowStart[i] = sb[threadIdx.x] - v;       // exclusive
    if (threadIdx.x == 1023) g_blockSums[blockIdx.x] = sb[1023];
}

__global__ void scan2_kernel() {   // 1 block, 128 threads
    __shared__ int sb[128];
    int v = (threadIdx.x < NB_SCAN) ? g_blockSums[threadIdx.x] : 0;
    sb[threadIdx.x] = v;
    __syncthreads();
    for (int off = 1; off < 128; off <<= 1) {
        int t = (threadIdx.x >= off) ? sb[threadIdx.x - off] : 0;
        __syncthreads();
        sb[threadIdx.x] += t;
        __syncthreads();
    }
    if (threadIdx.x < NB_SCAN) g_blockOffs[threadIdx.x] = sb[threadIdx.x] - v;
    if (threadIdx.x == 127) g_rowStart[NN] = sb[127];
}

__global__ void scan3_kernel() {
    int i = blockIdx.x * 1024 + threadIdx.x;
    if (i < NN) {
        int r = g_rowStart[i] + g_blockOffs[blockIdx.x];
        g_rowStart[i] = r;
        g_cursor[i]   = r;
    }
}

__global__ void scatter_kernel(const int* __restrict__ src, const int* __restrict__ dst) {
    for (int i = blockIdx.x * blockDim.x + threadIdx.x; i < NE; i += gridDim.x * blockDim.x) {
        int s = src[i], d = dst[i];
        float w = -g_dinv[s] * g_dinv[d];
        int p = atomicAdd(&g_cursor[d], 1);
        g_srcA[p] = s;
        g_wA[p]   = w;
    }
}

// ---------------- 64-wide propagation: out = a*(L_hat @ h) + b*prev ----------------
// 2 nodes/warp, 16 lanes/node. Phase = 16 edges: one coalesced CSR load per lane,
// then 16 shfl-broadcast gathers (independent LDG.128s back-to-back). Double-buffered.
__global__ void __launch_bounds__(256) prop64_kernel(
    const float* __restrict__ xin, int hsel, int psel, int osel, float a, float b)
{
    const float* h    = pick(hsel, xin);
    const float* prev = pick(psel, xin);
    float* out        = pickw(osel, nullptr);

    int warp = (blockIdx.x * blockDim.x + threadIdx.x) >> 5;
    int lane = threadIdx.x & 31;
    int sub  = lane >> 4;
    int l16  = lane & 15;
    int n    = warp * 2 + sub;          // NN even: all warps full
    unsigned gmask = 0xFFFFu << (sub * 16);

    int s = g_rowStart[n];
    int e = g_rowStart[n + 1];

    float4 acc = make_float4(0.f, 0.f, 0.f, 0.f);

    int j   = s;
    int cnt = e - j; if (cnt > 16) cnt = 16; if (cnt < 0) cnt = 0;
    int   idx = 0; float wv = 0.f;
    if (l16 < cnt) { idx = g_srcA[j + l16]; wv = g_wA[j + l16]; }

    while (cnt > 0) {
        int jn   = j + 16;
        int cnt2 = e - jn; if (cnt2 > 16) cnt2 = 16; if (cnt2 < 0) cnt2 = 0;
        int   idx2 = 0; float wv2 = 0.f;
        if (l16 < cnt2) { idx2 = g_srcA[jn + l16]; wv2 = g_wA[jn + l16]; }

        if (cnt == 16) {
#pragma unroll
            for (int t = 0; t < 16; t++) {
                int   si = __shfl_sync(gmask, idx, t, 16);
                float sw = __shfl_sync(gmask, wv,  t, 16);
                float4 v = *(const float4*)(h + (size_t)si * FDIM + l16 * 4);
                acc.x += sw * v.x; acc.y += sw * v.y;
                acc.z += sw * v.z; acc.w += sw * v.w;
            }
        } else {
            for (int t = 0; t < cnt; t++) {
                int   si = __shfl_sync(gmask, idx, t, 16);
                float sw = __shfl_sync(gmask, wv,  t, 16);
                float4 v = *(const float4*)(h + (size_t)si * FDIM + l16 * 4);
                acc.x += sw * v.x; acc.y += sw * v.y;
                acc.z += sw * v.z; acc.w += sw * v.w;
            }
        }
        j = jn; cnt = cnt2; idx = idx2; wv = wv2;
    }

    float4 r = make_float4(a * acc.x, a * acc.y, a * acc.z, a * acc.w);
    if (b != 0.0f) {
        float4 p = *(const float4*)(prev + (size_t)n * FDIM + l16 * 4);
        r.x += b * p.x; r.y += b * p.y; r.z += b * p.z; r.w += b * p.w;
    }
    *(float4*)(out + (size_t)n * FDIM + l16 * 4) = r;
}

// ---------------- 8-wide propagation (layer 2 after W2 projection) ----------------
// 4 nodes/warp, 8 lanes/node, phase = 8 edges via shfl broadcast.
// fuse: emits out[n,c] = t3[n,6+c] + t2[n,4+c] + t1[n,2+c] + Z[n,c]
__global__ void __launch_bounds__(256) prop8_kernel(
    int hsel, int psel, int osel, float a, float b, int fuse, float* __restrict__ fout)
{
    const float* h    = pick(hsel, nullptr);
    const float* prev = pick(psel, nullptr);
    float* out        = pickw(osel, nullptr);

    int warp = (blockIdx.x * blockDim.x + threadIdx.x) >> 5;
    int lane = threadIdx.x & 31;
    int sub  = lane >> 3;
    int l8   = lane & 7;
    int n    = warp * 4 + sub;          // NN % 4 == 0: all warps full
    unsigned gmask = 0xFFu << (sub * 8);

    int s = g_rowStart[n];
    int e = g_rowStart[n + 1];

    float acc = 0.0f;

    int j   = s;
    int cnt = e - j; if (cnt > 8) cnt = 8; if (cnt < 0) cnt = 0;
    int   idx = 0; float wv = 0.f;
    if (l8 < cnt) { idx = g_srcA[j + l8]; wv = g_wA[j + l8]; }

    while (cnt > 0) {
        int jn   = j + 8;
        int cnt2 = e - jn; if (cnt2 > 8) cnt2 = 8; if (cnt2 < 0) cnt2 = 0;
        int   idx2 = 0; float wv2 = 0.f;
        if (l8 < cnt2) { idx2 = g_srcA[jn + l8]; wv2 = g_wA[jn + l8]; }

        if (cnt == 8) {
#pragma unroll
            for (int t = 0; t < 8; t++) {
                int   si = __shfl_sync(gmask, idx, t, 8);
                float sw = __shfl_sync(gmask, wv,  t, 8);
                acc += sw * h[(size_t)si * 8 + l8];
            }
        } else {
            for (int t = 0; t < cnt; t++) {
                int   si = __shfl_sync(gmask, idx, t, 8);
                float sw = __shfl_sync(gmask, wv,  t, 8);
                acc += sw * h[(size_t)si * 8 + l8];
            }
        }
        j = jn; cnt = cnt2; idx = idx2; wv = wv2;
    }

    float r = a * acc;
    if (b != 0.0f) r += b * prev[(size_t)n * 8 + l8];

    if (!fuse) {
        out[(size_t)n * 8 + l8] = r;
    } else {
        // r = t3[n, l8]; pull col (6+c) of t3 into lanes c=0,1 of each subgroup
        float t3v = __shfl_sync(0xFFFFFFFFu, r, (lane & ~7) + 6 + l8);
        if (l8 < 2) {
            float o = t3v
                    + h   [(size_t)n * 8 + 4 + l8]   // t2[n,4+c]
                    + prev[(size_t)n * 8 + 2 + l8]   // t1[n,2+c]
                    + g_B1[(size_t)n * 8 + l8];      // Z[n,c]
            fout[(size_t)n * 2 + l8] = o;
        }
    }
}

// ---------------- layer-1 combine (+fused Z projection) ----------------
// H = relu(sum_k T_k @ W1_k); Z[n, 2k+c] = sum_i H[n,i] * W2[k,i,c] -> g_B1 [N,8]
__global__ void __launch_bounds__(256) combine64_kernel(
    const float* __restrict__ xin, int s0, int s1, int s2, int s3,
    const float* __restrict__ W, const float* __restrict__ W2, int osel)
{
    __shared__ float sW[64 * 64];
    __shared__ float sT[64][68];
    __shared__ float sW2[512];
    __shared__ float sZ[64][4][8];

    const float* ts0 = pick(s0, xin);
    const float* ts1 = pick(s1, xin);
    const float* ts2 = pick(s2, xin);
    const float* ts3 = pick(s3, xin);
    float* out = pickw(osel, nullptr);

    int tid   = threadIdx.x;
    int nodeL = tid >> 2;
    int jq    = tid & 3;
    int n0    = blockIdx.x * 64;

    for (int i = tid; i < 512; i += 256) sW2[i] = W2[i];

    float acc[16];
#pragma unroll
    for (int q = 0; q < 16; q++) acc[q] = 0.0f;

#pragma unroll
    for (int k = 0; k < 4; k++) {
        const float* tk = (k == 0) ? ts0 : (k == 1) ? ts1 : (k == 2) ? ts2 : ts3;
        const float4* Wk4 = (const float4*)(W + k * 4096);
#pragma unroll
        for (int i = tid; i < 1024; i += 256) ((float4*)sW)[i] = Wk4[i];
        const float4* tk4 = (const float4*)tk;
#pragma unroll
        for (int i = tid; i < 1024; i += 256) {
            int node = i >> 4, c4 = i & 15;
            float4 v = make_float4(0.f, 0.f, 0.f, 0.f);
            if (n0 + node < NN) v = tk4[(size_t)(n0 + node) * 16 + c4];
            *(float4*)&sT[node][c4 * 4] = v;
        }
        __syncthreads();

#pragma unroll
        for (int i4 = 0; i4 < 16; i4++) {
            float4 t = *(const float4*)&sT[nodeL][i4 * 4];
#pragma unroll
            for (int c = 0; c < 4; c++) {
                float tv = (c == 0) ? t.x : (c == 1) ? t.y : (c == 2) ? t.z : t.w;
                const float4* wr = (const float4*)(sW + (i4 * 4 + c) * 64 + jq * 16);
                float4 w0 = wr[0], w1 = wr[1], w2 = wr[2], w3 = wr[3];
                acc[0]  += tv * w0.x; acc[1]  += tv * w0.y; acc[2]  += tv * w0.z; acc[3]  += tv * w0.w;
                acc[4]  += tv * w1.x; acc[5]  += tv * w1.y; acc[6]  += tv * w1.z; acc[7]  += tv * w1.w;
                acc[8]  += tv * w2.x; acc[9]  += tv * w2.y; acc[10] += tv * w2.z; acc[11] += tv * w2.w;
                acc[12] += tv * w3.x; acc[13] += tv * w3.y; acc[14] += tv * w3.z; acc[15] += tv * w3.w;
            }
        }
        __syncthreads();
    }

    // relu in-register
#pragma unroll
    for (int q = 0; q < 16; q++) acc[q] = fmaxf(acc[q], 0.0f);

    int n = n0 + nodeL;
    if (n < NN) {
        float4* o4 = (float4*)(out + (size_t)n * 64 + jq * 16);
#pragma unroll
        for (int q4 = 0; q4 < 4; q4++)
            o4[q4] = make_float4(acc[q4 * 4 + 0], acc[q4 * 4 + 1],
                                 acc[q4 * 4 + 2], acc[q4 * 4 + 3]);
    }

    // fused Z projection: partial over this thread's i-range (i = jq*16+q)
    float z[8];
#pragma unroll
    for (int r = 0; r < 8; r++) z[r] = 0.0f;
#pragma unroll
    for (int q = 0; q < 16; q++) {
        int i = jq * 16 + q;
        float hv = acc[q];
#pragma unroll
        for (int k = 0; k < 4; k++) {
            z[2 * k + 0] += hv * sW2[k * 128 + i * 2 + 0];
            z[2 * k + 1] += hv * sW2[k * 128 + i * 2 + 1];
        }
    }
#pragma unroll
    for (int r = 0; r < 8; r++) sZ[nodeL][jq][r] = z[r];
    __syncthreads();
    if (jq == 0 && n < NN) {
        float4 z0, z1;
        z0.x = sZ[nodeL][0][0] + sZ[nodeL][1][0] + sZ[nodeL][2][0] + sZ[nodeL][3][0];
        z0.y = sZ[nodeL][0][1] + sZ[nodeL][1][1] + sZ[nodeL][2][1] + sZ[nodeL][3][1];
        z0.z = sZ[nodeL][0][2] + sZ[nodeL][1][2] + sZ[nodeL][2][2] + sZ[nodeL][3][2];
        z0.w = sZ[nodeL][0][3] + sZ[nodeL][1][3] + sZ[nodeL][2][3] + sZ[nodeL][3][3];
        z1.x = sZ[nodeL][0][4] + sZ[nodeL][1][4] + sZ[nodeL][2][4] + sZ[nodeL][3][4];
        z1.y = sZ[nodeL][0][5] + sZ[nodeL][1][5] + sZ[nodeL][2][5] + sZ[nodeL][3][5];
        z1.z = sZ[nodeL][0][6] + sZ[nodeL][1][6] + sZ[nodeL][2][6] + sZ[nodeL][3][6];
        z1.w = sZ[nodeL][0][7] + sZ[nodeL][1][7] + sZ[nodeL][2][7] + sZ[nodeL][3][7];
        float4* zo = (float4*)(g_B1 + (size_t)n * 8);
        zo[0] = z0; zo[1] = z1;
    }
}

// ---------------- launcher ----------------
extern "C" void kernel_launch(void* const* d_in, const int* in_sizes, int n_in,
                              void* d_out, int out_size)
{
    const float* x   = (const float*)d_in[0];
    const int*   ei  = (const int*)d_in[1];
    const int*   src = ei;
    const int*   dst = ei + NE;
    const float* W1  = (const float*)d_in[2];
    const float* W2  = (const float*)d_in[3];
    float* out = (float*)d_out;

    const int TB = 256;
    int gN  = (NN + TB - 1) / TB;
    int gP  = ((NN / 2) * 32 + TB - 1) / TB;   // 2 nodes/warp (64-wide)
    int g8  = ((NN / 4) * 32 + TB - 1) / TB;   // 4 nodes/warp (8-wide)
    int gC  = (NN + 63) / 64;
    int gS  = 1184;

    // ---- CSR build (fresh every launch) ----
    zero_kernel<<<gN, TB>>>();
    hist_kernel<<<gS, TB>>>(src, dst);
    scan1_kernel<<<NB_SCAN, 1024>>>();         // scan + dinv fused
    scan2_kernel<<<1, 128>>>();
    scan3_kernel<<<NB_SCAN, 1024>>>();
    scatter_kernel<<<gS, TB>>>(src, dst);

    // ---- layer 1 ----
    prop64_kernel<<<gP, TB>>>(x, 0, 0, 1, 1.0f,  0.0f);     // B1 = L x
    prop64_kernel<<<gP, TB>>>(x, 1, 0, 2, 2.0f, -1.0f);     // B2 = 2 L B1 - x
    prop64_kernel<<<gP, TB>>>(x, 2, 1, 3, 2.0f, -1.0f);     // B3 = 2 L B2 - B1
    combine64_kernel<<<gC, TB>>>(x, 0, 1, 2, 3, W1, W2, 4); // H = relu(sum); B1 <- Z = H@[W2k]

    // ---- layer 2 (8-wide recurrence on Z) ----
    prop8_kernel<<<g8, TB>>>(1, 1, 2, 1.0f,  0.0f, 0, nullptr); // B2 = t1 = L Z
    prop8_kernel<<<g8, TB>>>(2, 1, 3, 2.0f, -1.0f, 0, nullptr); // B3 = t2 = 2 L t1 - Z
    prop8_kernel<<<g8, TB>>>(3, 2, 0, 2.0f, -1.0f, 1, out);     // t3 fused + final sum -> out
}

// round 7
// speedup vs baseline: 1.4307x; 1.4307x over previous
#include <cuda_runtime.h>
#include <cstdint>

#define NN 100000
#define NE 1600000
#define FDIM 64
#define NB_SCAN 98   // ceil(NN/1024)

// ---------------- scratch (no allocation allowed) ----------------
__device__ float g_B1[NN * FDIM];
__device__ float g_B2[NN * FDIM];
__device__ float g_B3[NN * FDIM];
__device__ float g_H [NN * FDIM];
__device__ int2  g_csr[NE];          // {src, weight-as-int-bits} sorted by dst
__device__ int   g_degS[NN];
__device__ int   g_cntD[NN];
__device__ int   g_rowStart[NN + 1];
__device__ int   g_cursor[NN];
__device__ int   g_blockSums[128];
__device__ int   g_blockOffs[128];
__device__ float g_dinv[NN];

__device__ __forceinline__ const float* pick(int s, const float* x) {
    switch (s) {
        case 1: return g_B1;
        case 2: return g_B2;
        case 3: return g_B3;
        case 4: return g_H;
        default: return x;
    }
}
__device__ __forceinline__ float* pickw(int s, float* o) {
    switch (s) {
        case 1: return g_B1;
        case 2: return g_B2;
        case 3: return g_B3;
        case 4: return g_H;
        default: return o;
    }
}

__device__ __forceinline__ uint32_t f2tf32(float x) {
    uint32_t u;
    asm("cvt.rna.tf32.f32 %0, %1;" : "=r"(u) : "f"(x));
    return u;
}

// ---------------- CSR build ----------------
__global__ void zero_kernel() {
    int i = blockIdx.x * blockDim.x + threadIdx.x;
    if (i < NN) { g_degS[i] = 0; g_cntD[i] = 0; }
}

__global__ void hist_kernel(const int* __restrict__ src, const int* __restrict__ dst) {
    for (int i = blockIdx.x * blockDim.x + threadIdx.x; i < NE; i += gridDim.x * blockDim.x) {
        atomicAdd(&g_degS[src[i]], 1);
        atomicAdd(&g_cntD[dst[i]], 1);
    }
}

// scan of cntD + dinv computation (fused)
__global__ void scan1_kernel() {
    __shared__ int sb[1024];
    int i = blockIdx.x * 1024 + threadIdx.x;
    if (i < NN) {
        int d = g_degS[i];
        g_dinv[i] = (d > 0) ? rsqrtf((float)d) : 0.0f;
    }
    int v = (i < NN) ? g_cntD[i] : 0;
    sb[threadIdx.x] = v;
    __syncthreads();
    for (int off = 1; off < 1024; off <<= 1) {
        int t = (threadIdx.x >= off) ? sb[threadIdx.x - off] : 0;
        __syncthreads();
        sb[threadIdx.x] += t;
        __syncthreads();
    }
    if (i < NN) g_rowStart[i] = sb[threadIdx.x] - v;
    if (threadIdx.x == 1023) g_blockSums[blockIdx.x] = sb[1023];
}

__global__ void scan2_kernel() {
    __shared__ int sb[128];
    int v = (threadIdx.x < NB_SCAN) ? g_blockSums[threadIdx.x] : 0;
    sb[threadIdx.x] = v;
    __syncthreads();
    for (int off = 1; off < 128; off <<= 1) {
        int t = (threadIdx.x >= off) ? sb[threadIdx.x - off] : 0;
        __syncthreads();
        sb[threadIdx.x] += t;
        __syncthreads();
    }
    if (threadIdx.x < NB_SCAN) g_blockOffs[threadIdx.x] = sb[threadIdx.x] - v;
    if (threadIdx.x == 127) g_rowStart[NN] = sb[127];
}

__global__ void scan3_kernel() {
    int i = blockIdx.x * 1024 + threadIdx.x;
    if (i < NN) {
        int r = g_rowStart[i] + g_blockOffs[blockIdx.x];
        g_rowStart[i] = r;
        g_cursor[i]   = r;
    }
}

__global__ void scatter_kernel(const int* __restrict__ src, const int* __restrict__ dst) {
    for (int i = blockIdx.x * blockDim.x + threadIdx.x; i < NE; i += gridDim.x * blockDim.x) {
        int s = src[i], d = dst[i];
        float w = -g_dinv[s] * g_dinv[d];
        int p = atomicAdd(&g_cursor[d], 1);
        g_csr[p] = make_int2(s, __float_as_int(w));
    }
}

// ---------------- 64-wide propagation (R5 form): out = a*(L_hat @ h) + b*prev ----------------
// 2 nodes/warp; 16 lanes/node; lane covers 4 cols via float4 (1 LDG.128 per edge-pair)
__global__ void __launch_bounds__(256) prop64_kernel(
    const float* __restrict__ xin, int hsel, int psel, int osel, float a, float b)
{
    const float* h    = pick(hsel, xin);
    const float* prev = pick(psel, xin);
    float* out        = pickw(osel, nullptr);

    int warp = (blockIdx.x * blockDim.x + threadIdx.x) >> 5;
    int lane = threadIdx.x & 31;
    int sub  = lane >> 4;
    int l16  = lane & 15;
    int n    = warp * 2 + sub;
    if (n >= NN) return;

    int s = g_rowStart[n];
    int e = g_rowStart[n + 1];

    float4 acc = make_float4(0.f, 0.f, 0.f, 0.f);
    int j = s;
    // parity peel so int4 loads of g_csr are 16B-aligned
    if ((j & 1) && j < e) {
        int2 c = g_csr[j];
        float w = __int_as_float(c.y);
        float4 v = *(const float4*)(h + (size_t)c.x * FDIM + l16 * 4);
        acc.x += w * v.x; acc.y += w * v.y; acc.z += w * v.z; acc.w += w * v.w;
        j++;
    }
    int e4 = j + ((e - j) & ~3);
    for (; j < e4; j += 4) {
        int4 c01 = *(const int4*)&g_csr[j];
        int4 c23 = *(const int4*)&g_csr[j + 2];
        float4 v0 = *(const float4*)(h + (size_t)c01.x * FDIM + l16 * 4);
        float4 v1 = *(const float4*)(h + (size_t)c01.z * FDIM + l16 * 4);
        float4 v2 = *(const float4*)(h + (size_t)c23.x * FDIM + l16 * 4);
        float4 v3 = *(const float4*)(h + (size_t)c23.z * FDIM + l16 * 4);
        float w0 = __int_as_float(c01.y);
        float w1 = __int_as_float(c01.w);
        float w2 = __int_as_float(c23.y);
        float w3 = __int_as_float(c23.w);
        acc.x += w0 * v0.x; acc.y += w0 * v0.y; acc.z += w0 * v0.z; acc.w += w0 * v0.w;
        acc.x += w1 * v1.x; acc.y += w1 * v1.y; acc.z += w1 * v1.z; acc.w += w1 * v1.w;
        acc.x += w2 * v2.x; acc.y += w2 * v2.y; acc.z += w2 * v2.z; acc.w += w2 * v2.w;
        acc.x += w3 * v3.x; acc.y += w3 * v3.y; acc.z += w3 * v3.z; acc.w += w3 * v3.w;
    }
    for (; j < e; j++) {
        int2 c = g_csr[j];
        float w = __int_as_float(c.y);
        float4 v = *(const float4*)(h + (size_t)c.x * FDIM + l16 * 4);
        acc.x += w * v.x; acc.y += w * v.y; acc.z += w * v.z; acc.w += w * v.w;
    }

    float4 r = make_float4(a * acc.x, a * acc.y, a * acc.z, a * acc.w);
    if (b != 0.0f) {
        float4 p = *(const float4*)(prev + (size_t)n * FDIM + l16 * 4);
        r.x += b * p.x; r.y += b * p.y; r.z += b * p.z; r.w += b * p.w;
    }
    *(float4*)(out + (size_t)n * FDIM + l16 * 4) = r;
}

// ---------------- 8-wide propagation (R5 form, layer 2 after W2 projection) ----------------
__global__ void __launch_bounds__(256) prop8_kernel(
    int hsel, int psel, int osel, float a, float b, int fuse, float* __restrict__ fout)
{
    const float* h    = pick(hsel, nullptr);
    const float* prev = pick(psel, nullptr);
    float* out        = pickw(osel, nullptr);

    int warp = (blockIdx.x * blockDim.x + threadIdx.x) >> 5;
    int lane = threadIdx.x & 31;
    int sub  = lane >> 3;
    int l8   = lane & 7;
    int n    = warp * 4 + sub;
    if (n >= NN) return;

    int s = g_rowStart[n];
    int e = g_rowStart[n + 1];

    float acc = 0.0f;
    int j  = s;
    int e4 = s + ((e - s) & ~3);
    for (; j < e4; j += 4) {
        int2 c0 = g_csr[j + 0];
        int2 c1 = g_csr[j + 1];
        int2 c2 = g_csr[j + 2];
        int2 c3 = g_csr[j + 3];
        float v0 = h[(size_t)c0.x * 8 + l8];
        float v1 = h[(size_t)c1.x * 8 + l8];
        float v2 = h[(size_t)c2.x * 8 + l8];
        float v3 = h[(size_t)c3.x * 8 + l8];
        acc += __int_as_float(c0.y) * v0;
        acc += __int_as_float(c1.y) * v1;
        acc += __int_as_float(c2.y) * v2;
        acc += __int_as_float(c3.y) * v3;
    }
    for (; j < e; j++) {
        int2 c = g_csr[j];
        acc += __int_as_float(c.y) * h[(size_t)c.x * 8 + l8];
    }

    float r = a * acc;
    if (b != 0.0f) r += b * prev[(size_t)n * 8 + l8];

    if (!fuse) {
        out[(size_t)n * 8 + l8] = r;
    } else {
        float t3v = __shfl_sync(0xFFFFFFFFu, r, (lane & ~7) + 6 + l8);
        if (l8 < 2) {
            float o = t3v
                    + h   [(size_t)n * 8 + 4 + l8]   // t2[n,4+c]
                    + prev[(size_t)n * 8 + 2 + l8]   // t1[n,2+c]
                    + g_B1[(size_t)n * 8 + l8];      // Z[n,c]
            fout[(size_t)n * 2 + l8] = o;
        }
    }
}

// ---------------- layer-1 combine via tf32 mma.sync (+fused Z projection) ----------------
// 256 thr = 8 warps. Warp w: rows (w>>1)*16, cols (w&1)*32 of the 64x64 output tile.
// H = relu(sum_k T_k @ W1_k); then Z[n,2k+c] = sum_i H[n,i]*W2[k,i,c] -> g_B1 [N,8]
#define SMS 68   // smem row stride (floats): conflict-free for both fragment patterns
__global__ void __launch_bounds__(256) combine64_kernel(
    const float* __restrict__ xin, int s0, int s1, int s2, int s3,
    const float* __restrict__ W, const float* __restrict__ W2, int osel)
{
    __shared__ float sW[64 * SMS];   // W1_k, tf32-rounded
    __shared__ float sT[64 * SMS];   // T_k tile, tf32-rounded; later reused for H
    __shared__ float sW2[512];
    __shared__ float sZ[64][4][8];

    const float* ts0 = pick(s0, xin);
    const float* ts1 = pick(s1, xin);
    const float* ts2 = pick(s2, xin);
    const float* ts3 = pick(s3, xin);
    float* out = pickw(osel, nullptr);

    int tid  = threadIdx.x;
    int wid  = tid >> 5;
    int lane = tid & 31;
    int g    = lane >> 2;     // fragment group id (0..7)
    int t4   = lane & 3;      // fragment thread-in-group (0..3)
    int R0   = (wid >> 1) * 16;
    int C0   = (wid & 1) * 32;
    int n0   = blockIdx.x * 64;

    for (int i = tid; i < 512; i += 256) sW2[i] = W2[i];

    float acc[4][4];
#pragma unroll
    for (int nt = 0; nt < 4; nt++)
#pragma unroll
        for (int q = 0; q < 4; q++) acc[nt][q] = 0.0f;

#pragma unroll
    for (int k = 0; k < 4; k++) {
        const float* tk = (k == 0) ? ts0 : (k == 1) ? ts1 : (k == 2) ? ts2 : ts3;
        const float* Wk = W + k * 4096;
        // stage W1_k and T_k (tf32-rounded), 16 elems each per thread
#pragma unroll
        for (int i = tid; i < 4096; i += 256) {
            int r = i >> 6, c = i & 63;
            sW[r * SMS + c] = __uint_as_float(f2tf32(Wk[i]));
            int node = n0 + r;
            float tv = (node < NN) ? tk[(size_t)node * 64 + c] : 0.0f;
            sT[r * SMS + c] = __uint_as_float(f2tf32(tv));
        }
        __syncthreads();

#pragma unroll
        for (int kk = 0; kk < 8; kk++) {
            int kb = kk * 8;
            uint32_t a0 = __float_as_uint(sT[(R0 + g)     * SMS + kb + t4]);
            uint32_t a1 = __float_as_uint(sT[(R0 + g + 8) * SMS + kb + t4]);
            uint32_t a2 = __float_as_uint(sT[(R0 + g)     * SMS + kb + t4 + 4]);
            uint32_t a3 = __float_as_uint(sT[(R0 + g + 8) * SMS + kb + t4 + 4]);
#pragma unroll
            for (int nt = 0; nt < 4; nt++) {
                int col = C0 + nt * 8 + g;
                uint32_t b0 = __float_as_uint(sW[(kb + t4)     * SMS + col]);
                uint32_t b1 = __float_as_uint(sW[(kb + t4 + 4) * SMS + col]);
                asm volatile(
                    "mma.sync.aligned.m16n8k8.row.col.f32.tf32.tf32.f32 "
                    "{%0,%1,%2,%3}, {%4,%5,%6,%7}, {%8,%9}, {%0,%1,%2,%3};"
                    : "+f"(acc[nt][0]), "+f"(acc[nt][1]),
                      "+f"(acc[nt][2]), "+f"(acc[nt][3])
                    : "r"(a0), "r"(a1), "r"(a2), "r"(a3), "r"(b0), "r"(b1));
            }
        }
        __syncthreads();
    }

    // relu + write H to global and to sT (reused as H tile for Z projection)
#pragma unroll
    for (int nt = 0; nt < 4; nt++) {
        int c0c = C0 + nt * 8 + 2 * t4;
        int r0  = R0 + g;
        int r1  = R0 + g + 8;
        float d0 = fmaxf(acc[nt][0], 0.f);
        float d1 = fmaxf(acc[nt][1], 0.f);
        float d2 = fmaxf(acc[nt][2], 0.f);
        float d3 = fmaxf(acc[nt][3], 0.f);
        sT[r0 * SMS + c0c]     = d0;
        sT[r0 * SMS + c0c + 1] = d1;
        sT[r1 * SMS + c0c]     = d2;
        sT[r1 * SMS + c0c + 1] = d3;
        if (n0 + r0 < NN) {
            out[(size_t)(n0 + r0) * 64 + c0c]     = d0;
            out[(size_t)(n0 + r0) * 64 + c0c + 1] = d1;
        }
        if (n0 + r1 < NN) {
            out[(size_t)(n0 + r1) * 64 + c0c]     = d2;
            out[(size_t)(n0 + r1) * 64 + c0c + 1] = d3;
        }
    }
    __syncthreads();

    // fused Z projection from smem H
    int nodeL = tid >> 2;
    int jq    = tid & 3;
    float z[8];
#pragma unroll
    for (int r = 0; r < 8; r++) z[r] = 0.0f;
#pragma unroll
    for (int q = 0; q < 16; q++) {
        int i = jq * 16 + q;
        float hv = sT[nodeL * SMS + i];
#pragma unroll
        for (int kk = 0; kk < 4; kk++) {
            z[2 * kk + 0] += hv * sW2[kk * 128 + i * 2 + 0];
            z[2 * kk + 1] += hv * sW2[kk * 128 + i * 2 + 1];
        }
    }
#pragma unroll
    for (int r = 0; r < 8; r++) sZ[nodeL][jq][r] = z[r];
    __syncthreads();
    int n = n0 + nodeL;
    if (jq == 0 && n < NN) {
        float4 z0, z1;
        z0.x = sZ[nodeL][0][0] + sZ[nodeL][1][0] + sZ[nodeL][2][0] + sZ[nodeL][3][0];
        z0.y = sZ[nodeL][0][1] + sZ[nodeL][1][1] + sZ[nodeL][2][1] + sZ[nodeL][3][1];
        z0.z = sZ[nodeL][0][2] + sZ[nodeL][1][2] + sZ[nodeL][2][2] + sZ[nodeL][3][2];
        z0.w = sZ[nodeL][0][3] + sZ[nodeL][1][3] + sZ[nodeL][2][3] + sZ[nodeL][3][3];
        z1.x = sZ[nodeL][0][4] + sZ[nodeL][1][4] + sZ[nodeL][2][4] + sZ[nodeL][3][4];
        z1.y = sZ[nodeL][0][5] + sZ[nodeL][1][5] + sZ[nodeL][2][5] + sZ[nodeL][3][5];
        z1.z = sZ[nodeL][0][6] + sZ[nodeL][1][6] + sZ[nodeL][2][6] + sZ[nodeL][3][6];
        z1.w = sZ[nodeL][0][7] + sZ[nodeL][1][7] + sZ[nodeL][2][7] + sZ[nodeL][3][7];
        float4* zo = (float4*)(g_B1 + (size_t)n * 8);
        zo[0] = z0; zo[1] = z1;
    }
}

// ---------------- launcher ----------------
extern "C" void kernel_launch(void* const* d_in, const int* in_sizes, int n_in,
                              void* d_out, int out_size)
{
    const float* x   = (const float*)d_in[0];
    const int*   ei  = (const int*)d_in[1];
    const int*   src = ei;
    const int*   dst = ei + NE;
    const float* W1  = (const float*)d_in[2];
    const float* W2  = (const float*)d_in[3];
    float* out = (float*)d_out;

    const int TB = 256;
    int gN  = (NN + TB - 1) / TB;
    int gP  = ((NN / 2) * 32 + TB - 1) / TB;
    int g8  = ((NN / 4) * 32 + TB - 1) / TB;
    int gC  = (NN + 63) / 64;
    int gS  = 1184;

    // ---- CSR build ----
    zero_kernel<<<gN, TB>>>();
    hist_kernel<<<gS, TB>>>(src, dst);
    scan1_kernel<<<NB_SCAN, 1024>>>();
    scan2_kernel<<<1, 128>>>();
    scan3_kernel<<<NB_SCAN, 1024>>>();
    scatter_kernel<<<gS, TB>>>(src, dst);

    // ---- layer 1 ----
    prop64_kernel<<<gP, TB>>>(x, 0, 0, 1, 1.0f,  0.0f);     // B1 = L x
    prop64_kernel<<<gP, TB>>>(x, 1, 0, 2, 2.0f, -1.0f);     // B2 = 2 L B1 - x
    prop64_kernel<<<gP, TB>>>(x, 2, 1, 3, 2.0f, -1.0f);     // B3 = 2 L B2 - B1
    combine64_kernel<<<gC, TB>>>(x, 0, 1, 2, 3, W1, W2, 4); // H = relu(sum); B1 <- Z

    // ---- layer 2 (8-wide recurrence on Z) ----
    prop8_kernel<<<g8, TB>>>(1, 1, 2, 1.0f,  0.0f, 0, nullptr); // B2 = t1 = L Z
    prop8_kernel<<<g8, TB>>>(2, 1, 3, 2.0f, -1.0f, 0, nullptr); // B3 = t2 = 2 L t1 - Z
    prop8_kernel<<<g8, TB>>>(3, 2, 0, 2.0f, -1.0f, 1, out);     // t3 fused + final -> out
}